// round 8
// baseline (speedup 1.0000x reference)
#include <cuda_runtime.h>

// Problem constants (fixed by reference setup_inputs)
#define Hh     32
#define EPB    2          // batch elements per block
#define TIN    999        // teacher-forced steps
#define STEPS  1999       // TIN + future(1000)
#define BATCH  1024

typedef unsigned long long u64;

// Named-barrier producer/consumer primitives (128 = block size)
#define BSYNC(id) asm volatile("bar.sync %0, 128;"   :: "n"(id) : "memory")
#define BARRV(id) asm volatile("bar.arrive %0, 128;" :: "n"(id) : "memory")

// Packed 2xfp32 FMA / ADD (sm_103a f32x2 pipe)
__device__ __forceinline__ u64 fma2(u64 a, u64 b, u64 c) {
    u64 d;
    asm("fma.rn.f32x2 %0, %1, %2, %3;" : "=l"(d) : "l"(a), "l"(b), "l"(c));
    return d;
}
__device__ __forceinline__ u64 add2(u64 a, u64 b) {
    u64 d;
    asm("add.rn.f32x2 %0, %1, %2;" : "=l"(d) : "l"(a), "l"(b));
    return d;
}
__device__ __forceinline__ float f2lo(u64 a) { return __uint_as_float((unsigned)a); }
__device__ __forceinline__ float f2hi(u64 a) { return __uint_as_float((unsigned)(a >> 32)); }

__device__ __forceinline__ float ex2a(float x) { float y; asm("ex2.approx.f32 %0, %1;" : "=f"(y) : "f"(x)); return y; }
__device__ __forceinline__ float rcpa(float x) { float y; asm("rcp.approx.f32 %0, %1;" : "=f"(y) : "f"(x)); return y; }

// sigmoid(x) = 1/(1 + 2^(-x*log2e)); ~1e-7 accurate
__device__ __forceinline__ float sigm(float x) {
    return rcpa(1.0f + ex2a(-1.4426950408889634f * x));
}
// tanh(x) = 1 - 2/(1 + 2^(2x*log2e)); ~1e-7 accurate
__device__ __forceinline__ float tanh_(float x) {
    return fmaf(-2.0f, rcpa(1.0f + ex2a(2.8853900817779268f * x)), 1.0f);
}

__global__ __launch_bounds__(128) void lstm_seq_kernel(
    const float* __restrict__ input,                                   // [B, TIN]
    const float* __restrict__ W_ih1, const float* __restrict__ W_hh1,  // [4H,1], [4H,H]
    const float* __restrict__ b_ih1, const float* __restrict__ b_hh1,  // [4H]
    const float* __restrict__ W_ih2, const float* __restrict__ W_hh2,  // [4H,H], [4H,H]
    const float* __restrict__ b_ih2, const float* __restrict__ b_hh2,  // [4H]
    const float* __restrict__ W_lin, const float* __restrict__ b_lin,  // [1,H], [1]
    float* __restrict__ out)                                           // [B, STEPS]
{
    __shared__ float sh_in[EPB][TIN];                       // staged input rows (~8KB)
    __shared__ __align__(16) float sh_h1[EPB][Hh];
    __shared__ __align__(16) float sh_h2[EPB][Hh];
    __shared__ float sh_zA[EPB][4 * Hh];                    // layer-1 pre-activations
    __shared__ float sh_zB[EPB][4 * Hh];                    // layer-2 pre-activations
    __shared__ float sh_x[EPB];                             // fed-back output

    const int r    = threadIdx.x;        // gate row 0..127
    const int lane = r & 31;
    const int b0   = blockIdx.x * EPB;
    const bool front = (r < 64);         // warps 0,1: combine/head duty

    // combine-phase ownership (front threads): (element ce, unit cj)
    const int ce = r >> 5;               // valid when front (EPB==2)
    const int cj = lane;

    // ---- Weights into registers (packed pairs along k) ----
    const float wih1 = W_ih1[r];
    const float bb1  = b_ih1[r] + b_hh1[r];
    const float bb2  = b_ih2[r] + b_hh2[r];
    const float wlin = W_lin[lane];
    const float blin = b_lin[0];

    u64 whh1p[Hh / 2], wih2p[Hh / 2], whh2p[Hh / 2];
    {
        const u64* p1 = (const u64*)(W_hh1 + r * Hh);  // rows are 128B -> 8B aligned
        const u64* p2 = (const u64*)(W_ih2 + r * Hh);
        const u64* p3 = (const u64*)(W_hh2 + r * Hh);
#pragma unroll
        for (int i = 0; i < Hh / 2; i++) { whh1p[i] = p1[i]; wih2p[i] = p2[i]; whh2p[i] = p3[i]; }
    }

    // ---- Stage input rows into SMEM ----
#pragma unroll
    for (int e = 0; e < EPB; e++)
        for (int t = r; t < TIN; t += 128)
            sh_in[e][t] = input[(b0 + e) * TIN + t];

    // ---- Zero initial state; cell states live in front threads' registers ----
    if (front) { sh_h1[ce][cj] = 0.0f; sh_h2[ce][cj] = 0.0f; }
    float c1 = 0.0f, c2 = 0.0f;
    __syncthreads();

    // ============== Teacher-forced phase ==============
    // Barriers: A(id1) sync front / arrive back; B(id2) full; C(id3) sync front / arrive back.
    // Back warps (w2,w3) block ONLY at B; they run P1(t+1) while front does P4+head.
#pragma unroll 1
    for (int t = 0; t < TIN; t++) {
        // P1: layer-1 gate pre-activations (all threads)
#pragma unroll
        for (int e = 0; e < EPB; e++) {
            float x = sh_in[e][t];
            const ulonglong2* hp = (const ulonglong2*)sh_h1[e];   // broadcast LDS.128
            u64 a0 = 0ull, a1 = 0ull;
#pragma unroll
            for (int i = 0; i < 8; i++) {
                ulonglong2 hv = hp[i];
                a0 = fma2(whh1p[2 * i],     hv.x, a0);
                a1 = fma2(whh1p[2 * i + 1], hv.y, a1);
            }
            u64 s = add2(a0, a1);
            sh_zA[e][r] = fmaf(wih1, x, bb1) + (f2lo(s) + f2hi(s));
        }

        if (front) {
            BSYNC(1);                    // A: wait for all z1
            // P2: layer-1 combine
            float zi = sh_zA[ce][cj],          zf = sh_zA[ce][Hh + cj];
            float zg = sh_zA[ce][2 * Hh + cj], zo = sh_zA[ce][3 * Hh + cj];
            float cn = fmaf(sigm(zf), c1, sigm(zi) * tanh_(zg));
            c1 = cn;
            sh_h1[ce][cj] = sigm(zo) * tanh_(cn);
        } else {
            BARRV(1);                    // A: signal only, don't block
        }
        BSYNC(2);                        // B: h1_new visible to all

        // P3: layer-2 gate pre-activations (all threads)
#pragma unroll
        for (int e = 0; e < EPB; e++) {
            const ulonglong2* h1p = (const ulonglong2*)sh_h1[e];
            const ulonglong2* h2p = (const ulonglong2*)sh_h2[e];
            u64 a0 = 0ull, a1 = 0ull, a2 = 0ull, a3 = 0ull;
#pragma unroll
            for (int i = 0; i < 8; i++) {
                ulonglong2 hv1 = h1p[i];
                ulonglong2 hv2 = h2p[i];
                a0 = fma2(wih2p[2 * i],     hv1.x, a0);
                a1 = fma2(wih2p[2 * i + 1], hv1.y, a1);
                a2 = fma2(whh2p[2 * i],     hv2.x, a2);
                a3 = fma2(whh2p[2 * i + 1], hv2.y, a3);
            }
            u64 s = add2(add2(a0, a1), add2(a2, a3));
            sh_zB[e][r] = bb2 + (f2lo(s) + f2hi(s));
        }

        if (front) {
            BSYNC(3);                    // C: wait for all z2
            // P4: layer-2 combine + head; back warps already running P1(t+1)
            float zi = sh_zB[ce][cj],          zf = sh_zB[ce][Hh + cj];
            float zg = sh_zB[ce][2 * Hh + cj], zo = sh_zB[ce][3 * Hh + cj];
            float cn = fmaf(sigm(zf), c2, sigm(zi) * tanh_(zg));
            c2 = cn;
            float hn = sigm(zo) * tanh_(cn);
            sh_h2[ce][cj] = hn;

            float p = wlin * hn;
#pragma unroll
            for (int off = 16; off; off >>= 1)
                p += __shfl_xor_sync(0xffffffffu, p, off);
            if (cj == 0) {
                float o = p + blin;
                sh_x[ce] = o;            // seeds gen phase (D sync covers it)
                out[(size_t)(b0 + ce) * STEPS + t] = o;
            }
        } else {
            BARRV(3);                    // C: signal and run ahead into P1(t+1)
        }
    }

    // ============== Autoregressive phase ==============
    // Extra barrier D(id4, full): publishes sh_x; the expensive hh-dot runs BEFORE it.
#pragma unroll 1
    for (int t = TIN; t < STEPS; t++) {
        // P1a: hh1 dot (x-independent) — overlaps front's P4(t-1)+head
        float dsum[EPB];
#pragma unroll
        for (int e = 0; e < EPB; e++) {
            const ulonglong2* hp = (const ulonglong2*)sh_h1[e];
            u64 a0 = 0ull, a1 = 0ull;
#pragma unroll
            for (int i = 0; i < 8; i++) {
                ulonglong2 hv = hp[i];
                a0 = fma2(whh1p[2 * i],     hv.x, a0);
                a1 = fma2(whh1p[2 * i + 1], hv.y, a1);
            }
            u64 s = add2(a0, a1);
            dsum[e] = f2lo(s) + f2hi(s);
        }
        BSYNC(4);                        // D: sh_x(t-1) visible

        // P1b: fold in fed-back x, publish z1
#pragma unroll
        for (int e = 0; e < EPB; e++)
            sh_zA[e][r] = fmaf(wih1, sh_x[e], bb1) + dsum[e];

        if (front) {
            BSYNC(1);
            float zi = sh_zA[ce][cj],          zf = sh_zA[ce][Hh + cj];
            float zg = sh_zA[ce][2 * Hh + cj], zo = sh_zA[ce][3 * Hh + cj];
            float cn = fmaf(sigm(zf), c1, sigm(zi) * tanh_(zg));
            c1 = cn;
            sh_h1[ce][cj] = sigm(zo) * tanh_(cn);
        } else {
            BARRV(1);
        }
        BSYNC(2);

#pragma unroll
        for (int e = 0; e < EPB; e++) {
            const ulonglong2* h1p = (const ulonglong2*)sh_h1[e];
            const ulonglong2* h2p = (const ulonglong2*)sh_h2[e];
            u64 a0 = 0ull, a1 = 0ull, a2 = 0ull, a3 = 0ull;
#pragma unroll
            for (int i = 0; i < 8; i++) {
                ulonglong2 hv1 = h1p[i];
                ulonglong2 hv2 = h2p[i];
                a0 = fma2(wih2p[2 * i],     hv1.x, a0);
                a1 = fma2(wih2p[2 * i + 1], hv1.y, a1);
                a2 = fma2(whh2p[2 * i],     hv2.x, a2);
                a3 = fma2(whh2p[2 * i + 1], hv2.y, a3);
            }
            u64 s = add2(add2(a0, a1), add2(a2, a3));
            sh_zB[e][r] = bb2 + (f2lo(s) + f2hi(s));
        }

        if (front) {
            BSYNC(3);
            float zi = sh_zB[ce][cj],          zf = sh_zB[ce][Hh + cj];
            float zg = sh_zB[ce][2 * Hh + cj], zo = sh_zB[ce][3 * Hh + cj];
            float cn = fmaf(sigm(zf), c2, sigm(zi) * tanh_(zg));
            c2 = cn;
            float hn = sigm(zo) * tanh_(cn);
            sh_h2[ce][cj] = hn;

            float p = wlin * hn;
#pragma unroll
            for (int off = 16; off; off >>= 1)
                p += __shfl_xor_sync(0xffffffffu, p, off);
            if (cj == 0) {
                float o = p + blin;
                sh_x[ce] = o;
                out[(size_t)(b0 + ce) * STEPS + t] = o;
            }
        } else {
            BARRV(3);                    // run ahead into P1a(t+1)
        }
    }
}

extern "C" void kernel_launch(void* const* d_in, const int* in_sizes, int n_in,
                              void* d_out, int out_size) {
    const float* input = (const float*)d_in[0];
    const float* W_ih1 = (const float*)d_in[1];
    const float* W_hh1 = (const float*)d_in[2];
    const float* b_ih1 = (const float*)d_in[3];
    const float* b_hh1 = (const float*)d_in[4];
    const float* W_ih2 = (const float*)d_in[5];
    const float* W_hh2 = (const float*)d_in[6];
    const float* b_ih2 = (const float*)d_in[7];
    const float* b_hh2 = (const float*)d_in[8];
    const float* W_lin = (const float*)d_in[9];
    const float* b_lin = (const float*)d_in[10];
    float* out = (float*)d_out;

    lstm_seq_kernel<<<BATCH / EPB, 128>>>(input, W_ih1, W_hh1, b_ih1, b_hh1,
                                          W_ih2, W_hh2, b_ih2, b_hh2,
                                          W_lin, b_lin, out);
}

// round 9
// speedup vs baseline: 1.0337x; 1.0337x over previous
#include <cuda_runtime.h>

// Problem constants (fixed by reference setup_inputs)
#define Hh     32
#define EPB    8          // batch elements per block (1 block/SM)
#define TIN    999        // teacher-forced input length
#define TFE    998        // TF steps done in TF loop (t=998 handled by gen loop)
#define STEPS  1999       // TIN + future(1000)
#define BATCH  1024

typedef unsigned long long u64;

// Scratch: h2 history for the TF phase (head applied by head_kernel)
__device__ float H2g[(size_t)BATCH * TFE * Hh];   // ~128 MB static scratch

// Packed 2xfp32 FMA / ADD (sm_103a f32x2 pipe)
__device__ __forceinline__ u64 fma2(u64 a, u64 b, u64 c) {
    u64 d;
    asm("fma.rn.f32x2 %0, %1, %2, %3;" : "=l"(d) : "l"(a), "l"(b), "l"(c));
    return d;
}
__device__ __forceinline__ u64 add2(u64 a, u64 b) {
    u64 d;
    asm("add.rn.f32x2 %0, %1, %2;" : "=l"(d) : "l"(a), "l"(b));
    return d;
}
__device__ __forceinline__ float f2lo(u64 a) { return __uint_as_float((unsigned)a); }
__device__ __forceinline__ float f2hi(u64 a) { return __uint_as_float((unsigned)(a >> 32)); }

__device__ __forceinline__ float ex2a(float x) { float y; asm("ex2.approx.f32 %0, %1;" : "=f"(y) : "f"(x)); return y; }
__device__ __forceinline__ float rcpa(float x) { float y; asm("rcp.approx.f32 %0, %1;" : "=f"(y) : "f"(x)); return y; }

// sigmoid(x) = 1/(1 + 2^(-x*log2e)); ~1e-7 accurate
__device__ __forceinline__ float sigm(float x) {
    return rcpa(1.0f + ex2a(-1.4426950408889634f * x));
}
// tanh(x) = 1 - 2/(1 + 2^(2x*log2e)); ~1e-7 accurate
__device__ __forceinline__ float tanh_(float x) {
    return fmaf(-2.0f, rcpa(1.0f + ex2a(2.8853900817779268f * x)), 1.0f);
}

__global__ __launch_bounds__(128) void lstm_seq_kernel(
    const float* __restrict__ input,
    const float* __restrict__ W_ih1, const float* __restrict__ W_hh1,
    const float* __restrict__ b_ih1, const float* __restrict__ b_hh1,
    const float* __restrict__ W_ih2, const float* __restrict__ W_hh2,
    const float* __restrict__ b_ih2, const float* __restrict__ b_hh2,
    const float* __restrict__ W_lin, const float* __restrict__ b_lin,
    float* __restrict__ out)
{
    __shared__ float sh_in[EPB][TIN];                     // ~32 KB staged inputs
    __shared__ __align__(16) float sh_h1[EPB][Hh];
    __shared__ __align__(16) float sh_h2[EPB][Hh];
    __shared__ float sh_zA[EPB][4 * Hh];
    __shared__ float sh_zB[EPB][4 * Hh];
    __shared__ float sh_x[EPB];

    const int r    = threadIdx.x;        // gate row 0..127
    const int w    = r >> 5;             // warp 0..3
    const int lane = r & 31;
    const int b0   = blockIdx.x * EPB;

    // Combine tasks: thread r owns (eA = w, j = lane) and (eB = w+4, j = lane)
    const int eA = w, eB = w + 4, j = lane;

    // ---- Weights into registers (packed pairs along k) ----
    const float wih1 = W_ih1[r];
    const float bb1  = b_ih1[r] + b_hh1[r];
    const float bb2  = b_ih2[r] + b_hh2[r];
    const float wlin = W_lin[lane];
    const float blin = b_lin[0];

    u64 whh1p[Hh / 2], wih2p[Hh / 2], whh2p[Hh / 2];
    {
        const u64* p1 = (const u64*)(W_hh1 + r * Hh);
        const u64* p2 = (const u64*)(W_ih2 + r * Hh);
        const u64* p3 = (const u64*)(W_hh2 + r * Hh);
#pragma unroll
        for (int i = 0; i < Hh / 2; i++) { whh1p[i] = p1[i]; wih2p[i] = p2[i]; whh2p[i] = p3[i]; }
    }

    // ---- Stage input rows into SMEM ----
#pragma unroll
    for (int e = 0; e < EPB; e++)
        for (int t = r; t < TIN; t += 128)
            sh_in[e][t] = input[(b0 + e) * TIN + t];

    // ---- Zero initial state; cell states in task-owner registers ----
    sh_h1[eA][j] = 0.0f;  sh_h1[eB][j] = 0.0f;
    sh_h2[eA][j] = 0.0f;  sh_h2[eB][j] = 0.0f;
    float c1A = 0.0f, c1B = 0.0f, c2A = 0.0f, c2B = 0.0f;
    __syncthreads();

    // ================= Teacher-forced phase: 3 barriers/step, head deferred =================
#pragma unroll 1
    for (int t = 0; t < TFE; t++) {
        // P1: layer-1 gate pre-activations (8 independent elements of ILP)
#pragma unroll
        for (int e = 0; e < EPB; e++) {
            float x = sh_in[e][t];
            const ulonglong2* hp = (const ulonglong2*)sh_h1[e];   // broadcast LDS.128
            u64 a0 = 0ull, a1 = 0ull;
#pragma unroll
            for (int i = 0; i < 8; i++) {
                ulonglong2 hv = hp[i];
                a0 = fma2(whh1p[2 * i],     hv.x, a0);
                a1 = fma2(whh1p[2 * i + 1], hv.y, a1);
            }
            u64 s = add2(a0, a1);
            sh_zA[e][r] = fmaf(wih1, x, bb1) + (f2lo(s) + f2hi(s));
        }
        __syncthreads();

        // P2: layer-1 combine — 2 tasks per thread, all warps
        {
            float ziA = sh_zA[eA][j],          zfA = sh_zA[eA][Hh + j];
            float zgA = sh_zA[eA][2 * Hh + j], zoA = sh_zA[eA][3 * Hh + j];
            float ziB = sh_zA[eB][j],          zfB = sh_zA[eB][Hh + j];
            float zgB = sh_zA[eB][2 * Hh + j], zoB = sh_zA[eB][3 * Hh + j];
            float cnA = fmaf(sigm(zfA), c1A, sigm(ziA) * tanh_(zgA));
            float cnB = fmaf(sigm(zfB), c1B, sigm(ziB) * tanh_(zgB));
            c1A = cnA;  c1B = cnB;
            sh_h1[eA][j] = sigm(zoA) * tanh_(cnA);
            sh_h1[eB][j] = sigm(zoB) * tanh_(cnB);
        }
        __syncthreads();

        // P3: layer-2 gate pre-activations (16 independent dots of ILP)
#pragma unroll
        for (int e = 0; e < EPB; e++) {
            const ulonglong2* h1p = (const ulonglong2*)sh_h1[e];
            const ulonglong2* h2p = (const ulonglong2*)sh_h2[e];
            u64 a0 = 0ull, a1 = 0ull, a2 = 0ull, a3 = 0ull;
#pragma unroll
            for (int i = 0; i < 8; i++) {
                ulonglong2 hv1 = h1p[i];
                ulonglong2 hv2 = h2p[i];
                a0 = fma2(wih2p[2 * i],     hv1.x, a0);
                a1 = fma2(wih2p[2 * i + 1], hv1.y, a1);
                a2 = fma2(whh2p[2 * i],     hv2.x, a2);
                a3 = fma2(whh2p[2 * i + 1], hv2.y, a3);
            }
            u64 s = add2(add2(a0, a1), add2(a2, a3));
            sh_zB[e][r] = bb2 + (f2lo(s) + f2hi(s));
        }
        __syncthreads();

        // P4: layer-2 combine; h2 -> SMEM + deferred-head history. No barrier to next P1.
        {
            float ziA = sh_zB[eA][j],          zfA = sh_zB[eA][Hh + j];
            float zgA = sh_zB[eA][2 * Hh + j], zoA = sh_zB[eA][3 * Hh + j];
            float ziB = sh_zB[eB][j],          zfB = sh_zB[eB][Hh + j];
            float zgB = sh_zB[eB][2 * Hh + j], zoB = sh_zB[eB][3 * Hh + j];
            float cnA = fmaf(sigm(zfA), c2A, sigm(ziA) * tanh_(zgA));
            float cnB = fmaf(sigm(zfB), c2B, sigm(ziB) * tanh_(zgB));
            c2A = cnA;  c2B = cnB;
            float hnA = sigm(zoA) * tanh_(cnA);
            float hnB = sigm(zoB) * tanh_(cnB);
            sh_h2[eA][j] = hnA;
            sh_h2[eB][j] = hnB;
            H2g[((size_t)(b0 + eA) * TFE + t) * Hh + j] = hnA;   // coalesced 128B/warp
            H2g[((size_t)(b0 + eB) * TFE + t) * Hh + j] = hnB;
        }
    }

    // ================= Gen phase (incl. t=TFE with real input): 4 barriers/step =================
#pragma unroll 1
    for (int t = TFE; t < STEPS; t++) {
        // P1a: x-independent hh1 dots (reads sh_h1 — safe vs prior P4)
        float dsum[EPB];
#pragma unroll
        for (int e = 0; e < EPB; e++) {
            const ulonglong2* hp = (const ulonglong2*)sh_h1[e];
            u64 a0 = 0ull, a1 = 0ull;
#pragma unroll
            for (int i = 0; i < 8; i++) {
                ulonglong2 hv = hp[i];
                a0 = fma2(whh1p[2 * i],     hv.x, a0);
                a1 = fma2(whh1p[2 * i + 1], hv.y, a1);
            }
            u64 s = add2(a0, a1);
            dsum[e] = f2lo(s) + f2hi(s);
        }
        __syncthreads();                 // D: sh_x(t-1) visible (and orders prior P4)

        // P1b: fold in x, publish z1
#pragma unroll
        for (int e = 0; e < EPB; e++) {
            float x = (t == TFE) ? sh_in[e][TFE] : sh_x[e];
            sh_zA[e][r] = fmaf(wih1, x, bb1) + dsum[e];
        }
        __syncthreads();

        // P2
        {
            float ziA = sh_zA[eA][j],          zfA = sh_zA[eA][Hh + j];
            float zgA = sh_zA[eA][2 * Hh + j], zoA = sh_zA[eA][3 * Hh + j];
            float ziB = sh_zA[eB][j],          zfB = sh_zA[eB][Hh + j];
            float zgB = sh_zA[eB][2 * Hh + j], zoB = sh_zA[eB][3 * Hh + j];
            float cnA = fmaf(sigm(zfA), c1A, sigm(ziA) * tanh_(zgA));
            float cnB = fmaf(sigm(zfB), c1B, sigm(ziB) * tanh_(zgB));
            c1A = cnA;  c1B = cnB;
            sh_h1[eA][j] = sigm(zoA) * tanh_(cnA);
            sh_h1[eB][j] = sigm(zoB) * tanh_(cnB);
        }
        __syncthreads();

        // P3
#pragma unroll
        for (int e = 0; e < EPB; e++) {
            const ulonglong2* h1p = (const ulonglong2*)sh_h1[e];
            const ulonglong2* h2p = (const ulonglong2*)sh_h2[e];
            u64 a0 = 0ull, a1 = 0ull, a2 = 0ull, a3 = 0ull;
#pragma unroll
            for (int i = 0; i < 8; i++) {
                ulonglong2 hv1 = h1p[i];
                ulonglong2 hv2 = h2p[i];
                a0 = fma2(wih2p[2 * i],     hv1.x, a0);
                a1 = fma2(wih2p[2 * i + 1], hv1.y, a1);
                a2 = fma2(whh2p[2 * i],     hv2.x, a2);
                a3 = fma2(whh2p[2 * i + 1], hv2.y, a3);
            }
            u64 s = add2(add2(a0, a1), add2(a2, a3));
            sh_zB[e][r] = bb2 + (f2lo(s) + f2hi(s));
        }
        __syncthreads();

        // P4: combine + head (two interleaved 5-shfl reductions per warp)
        {
            float ziA = sh_zB[eA][j],          zfA = sh_zB[eA][Hh + j];
            float zgA = sh_zB[eA][2 * Hh + j], zoA = sh_zB[eA][3 * Hh + j];
            float ziB = sh_zB[eB][j],          zfB = sh_zB[eB][Hh + j];
            float zgB = sh_zB[eB][2 * Hh + j], zoB = sh_zB[eB][3 * Hh + j];
            float cnA = fmaf(sigm(zfA), c2A, sigm(ziA) * tanh_(zgA));
            float cnB = fmaf(sigm(zfB), c2B, sigm(ziB) * tanh_(zgB));
            c2A = cnA;  c2B = cnB;
            float hnA = sigm(zoA) * tanh_(cnA);
            float hnB = sigm(zoB) * tanh_(cnB);
            sh_h2[eA][j] = hnA;
            sh_h2[eB][j] = hnB;

            float pA = wlin * hnA;
            float pB = wlin * hnB;
#pragma unroll
            for (int off = 16; off; off >>= 1) {
                pA += __shfl_xor_sync(0xffffffffu, pA, off);
                pB += __shfl_xor_sync(0xffffffffu, pB, off);
            }
            if (j == 0) {
                float oA = pA + blin;
                float oB = pB + blin;
                sh_x[eA] = oA;
                sh_x[eB] = oB;
                out[(size_t)(b0 + eA) * STEPS + t] = oA;
                out[(size_t)(b0 + eB) * STEPS + t] = oB;
            }
        }
    }
}

// Apply linear head to stored TF h2 history: out[b][t] = W_lin @ H2g[b][t] + b_lin
__global__ __launch_bounds__(256) void head_kernel(
    const float* __restrict__ W_lin, const float* __restrict__ b_lin,
    float* __restrict__ out)
{
    const int b = blockIdx.x;
    float4 wv[8];
    const float4* wp = (const float4*)W_lin;
#pragma unroll
    for (int i = 0; i < 8; i++) wv[i] = wp[i];
    const float bl = b_lin[0];

    for (int t = threadIdx.x; t < TFE; t += 256) {
        const float4* hp = (const float4*)(H2g + ((size_t)b * TFE + t) * Hh);
        float acc = bl;
#pragma unroll
        for (int i = 0; i < 8; i++) {
            float4 h = hp[i];
            acc += wv[i].x * h.x + wv[i].y * h.y + wv[i].z * h.z + wv[i].w * h.w;
        }
        out[(size_t)b * STEPS + t] = acc;
    }
}

extern "C" void kernel_launch(void* const* d_in, const int* in_sizes, int n_in,
                              void* d_out, int out_size) {
    const float* input = (const float*)d_in[0];
    const float* W_ih1 = (const float*)d_in[1];
    const float* W_hh1 = (const float*)d_in[2];
    const float* b_ih1 = (const float*)d_in[3];
    const float* b_hh1 = (const float*)d_in[4];
    const float* W_ih2 = (const float*)d_in[5];
    const float* W_hh2 = (const float*)d_in[6];
    const float* b_ih2 = (const float*)d_in[7];
    const float* b_hh2 = (const float*)d_in[8];
    const float* W_lin = (const float*)d_in[9];
    const float* b_lin = (const float*)d_in[10];
    float* out = (float*)d_out;

    lstm_seq_kernel<<<BATCH / EPB, 128>>>(input, W_ih1, W_hh1, b_ih1, b_hh1,
                                          W_ih2, W_hh2, b_ih2, b_hh2,
                                          W_lin, b_lin, out);
    head_kernel<<<BATCH, 256>>>(W_lin, b_lin, out);
}

// round 10
// speedup vs baseline: 1.3554x; 1.3113x over previous
#include <cuda_runtime.h>

// Problem constants (fixed by reference setup_inputs)
#define Hh     32
#define EPB    2          // batch elements per block
#define TIN    999        // teacher-forced steps
#define STEPS  1999       // TIN + future(1000)
#define BATCH  1024

typedef unsigned long long u64;

// Scratch: h2 history for the TF phase (head applied by head_kernel) ~131 MB
__device__ float H2g[(size_t)BATCH * TIN * Hh];

// Packed 2xfp32 FMA / ADD (sm_103a f32x2 pipe)
__device__ __forceinline__ u64 fma2(u64 a, u64 b, u64 c) {
    u64 d;
    asm("fma.rn.f32x2 %0, %1, %2, %3;" : "=l"(d) : "l"(a), "l"(b), "l"(c));
    return d;
}
__device__ __forceinline__ u64 add2(u64 a, u64 b) {
    u64 d;
    asm("add.rn.f32x2 %0, %1, %2;" : "=l"(d) : "l"(a), "l"(b));
    return d;
}
__device__ __forceinline__ float f2lo(u64 a) { return __uint_as_float((unsigned)a); }
__device__ __forceinline__ float f2hi(u64 a) { return __uint_as_float((unsigned)(a >> 32)); }

__device__ __forceinline__ float ex2a(float x) { float y; asm("ex2.approx.f32 %0, %1;" : "=f"(y) : "f"(x)); return y; }
__device__ __forceinline__ float rcpa(float x) { float y; asm("rcp.approx.f32 %0, %1;" : "=f"(y) : "f"(x)); return y; }

// sigmoid(x) = 1/(1 + 2^(-x*log2e)); ~1e-7 accurate
__device__ __forceinline__ float sigm(float x) {
    return rcpa(1.0f + ex2a(-1.4426950408889634f * x));
}
// tanh(x) = 1 - 2/(1 + 2^(2x*log2e)); ~1e-7 accurate
__device__ __forceinline__ float tanh_(float x) {
    return fmaf(-2.0f, rcpa(1.0f + ex2a(2.8853900817779268f * x)), 1.0f);
}

__global__ __launch_bounds__(128, 4) void lstm_seq_kernel(
    const float* __restrict__ input,                                   // [B, TIN]
    const float* __restrict__ W_ih1, const float* __restrict__ W_hh1,  // [4H,1], [4H,H]
    const float* __restrict__ b_ih1, const float* __restrict__ b_hh1,  // [4H]
    const float* __restrict__ W_ih2, const float* __restrict__ W_hh2,  // [4H,H], [4H,H]
    const float* __restrict__ b_ih2, const float* __restrict__ b_hh2,  // [4H]
    const float* __restrict__ W_lin, const float* __restrict__ b_lin,  // [1,H], [1]
    float* __restrict__ out)                                           // [B, STEPS]
{
    __shared__ float sh_in[EPB][TIN];                       // staged input rows (~8KB)
    __shared__ __align__(16) float sh_h1[EPB][Hh];
    __shared__ __align__(16) float sh_h2[EPB][Hh];
    __shared__ float sh_zA[EPB][4 * Hh];                    // layer-1 pre-activations
    __shared__ float sh_zB[EPB][4 * Hh];                    // layer-2 pre-activations
    __shared__ __align__(16) float sh_wl[Hh];               // W_lin copy
    __shared__ float sh_wih1[4 * Hh];                       // W_ih1 copy (gen x-fold)

    const int r    = threadIdx.x;        // gate row 0..127
    const int lane = r & 31;
    const int b0   = blockIdx.x * EPB;
    const bool front = (r < 64);         // warps 0,1: combine duty

    const int ce = r >> 5;               // front-only: element 0/1
    const int cj = lane;                 // front-only: hidden unit

    // ---- Weights into registers (packed pairs along k) ----
    const float wih1 = W_ih1[r];
    const float bb1  = b_ih1[r] + b_hh1[r];
    const float bb2  = b_ih2[r] + b_hh2[r];
    const float blin = b_lin[0];

    u64 whh1p[Hh / 2], wih2p[Hh / 2], whh2p[Hh / 2];
    {
        const u64* p1 = (const u64*)(W_hh1 + r * Hh);  // rows are 128B -> 8B aligned
        const u64* p2 = (const u64*)(W_ih2 + r * Hh);
        const u64* p3 = (const u64*)(W_hh2 + r * Hh);
#pragma unroll
        for (int i = 0; i < Hh / 2; i++) { whh1p[i] = p1[i]; wih2p[i] = p2[i]; whh2p[i] = p3[i]; }
    }

    // ---- Stage input rows + weight copies into SMEM ----
#pragma unroll
    for (int e = 0; e < EPB; e++)
        for (int t = r; t < TIN; t += 128)
            sh_in[e][t] = input[(b0 + e) * TIN + t];
    if (r < Hh) sh_wl[r] = W_lin[r];
    sh_wih1[r] = wih1;

    if (front) { sh_h1[ce][cj] = 0.0f; sh_h2[ce][cj] = 0.0f; }
    float c1 = 0.0f, c2 = 0.0f;          // cell states of task (ce, cj), front only
    __syncthreads();

    // ================= Teacher-forced phase: 3 barriers/step, head deferred =================
#pragma unroll 1
    for (int t = 0; t < TIN; t++) {
        // P1: layer-1 gate pre-activations
#pragma unroll
        for (int e = 0; e < EPB; e++) {
            float x = sh_in[e][t];
            const ulonglong2* hp = (const ulonglong2*)sh_h1[e];   // broadcast LDS.128
            u64 a0 = 0ull, a1 = 0ull;
#pragma unroll
            for (int i = 0; i < 8; i++) {
                ulonglong2 hv = hp[i];
                a0 = fma2(whh1p[2 * i],     hv.x, a0);
                a1 = fma2(whh1p[2 * i + 1], hv.y, a1);
            }
            u64 s = add2(a0, a1);
            sh_zA[e][r] = fmaf(wih1, x, bb1) + (f2lo(s) + f2hi(s));
        }
        __syncthreads();                 // A

        // P2: layer-1 combine (warps 0-1)
        if (front) {
            float zi = sh_zA[ce][cj],          zf = sh_zA[ce][Hh + cj];
            float zg = sh_zA[ce][2 * Hh + cj], zo = sh_zA[ce][3 * Hh + cj];
            float cn = fmaf(sigm(zf), c1, sigm(zi) * tanh_(zg));
            c1 = cn;
            sh_h1[ce][cj] = sigm(zo) * tanh_(cn);
        }
        __syncthreads();                 // B

        // P3: layer-2 gate pre-activations
#pragma unroll
        for (int e = 0; e < EPB; e++) {
            const ulonglong2* h1p = (const ulonglong2*)sh_h1[e];
            const ulonglong2* h2p = (const ulonglong2*)sh_h2[e];
            u64 a0 = 0ull, a1 = 0ull, a2 = 0ull, a3 = 0ull;
#pragma unroll
            for (int i = 0; i < 8; i++) {
                ulonglong2 hv1 = h1p[i];
                ulonglong2 hv2 = h2p[i];
                a0 = fma2(wih2p[2 * i],     hv1.x, a0);
                a1 = fma2(wih2p[2 * i + 1], hv1.y, a1);
                a2 = fma2(whh2p[2 * i],     hv2.x, a2);
                a3 = fma2(whh2p[2 * i + 1], hv2.y, a3);
            }
            u64 s = add2(add2(a0, a1), add2(a2, a3));
            sh_zB[e][r] = bb2 + (f2lo(s) + f2hi(s));
        }
        __syncthreads();                 // C

        // P4: layer-2 combine + h2 history store. No head, no barrier (flows into P1).
        if (front) {
            float zi = sh_zB[ce][cj],          zf = sh_zB[ce][Hh + cj];
            float zg = sh_zB[ce][2 * Hh + cj], zo = sh_zB[ce][3 * Hh + cj];
            float cn = fmaf(sigm(zf), c2, sigm(zi) * tanh_(zg));
            c2 = cn;
            float hn = sigm(zo) * tanh_(cn);
            sh_h2[ce][cj] = hn;
            H2g[((size_t)(b0 + ce) * TIN + t) * Hh + cj] = hn;   // coalesced, fire-and-forget
        }
    }

    // ================= Gen phase: 3 barriers/step, feedback folded into P2 =================
#pragma unroll 1
    for (int t = TIN; t < STEPS; t++) {
        // P1: x-independent hh1 dot (sh_h1 stable since B(t-1); sh_h2 untouched here)
#pragma unroll
        for (int e = 0; e < EPB; e++) {
            const ulonglong2* hp = (const ulonglong2*)sh_h1[e];
            u64 a0 = 0ull, a1 = 0ull;
#pragma unroll
            for (int i = 0; i < 8; i++) {
                ulonglong2 hv = hp[i];
                a0 = fma2(whh1p[2 * i],     hv.x, a0);
                a1 = fma2(whh1p[2 * i + 1], hv.y, a1);
            }
            u64 s = add2(a0, a1);
            sh_zA[e][r] = bb1 + (f2lo(s) + f2hi(s));
        }
        __syncthreads();                 // A: z1-partials ready; h2(t-1) final (P4 pre-A)

        // P2: recompute feedback x = W_lin@h2(t-1) + b_lin, fold, combine, emit out[t-1]
        if (front) {
            const ulonglong2* wp = (const ulonglong2*)sh_wl;
            const ulonglong2* hp = (const ulonglong2*)sh_h2[ce];
            u64 a0 = 0ull, a1 = 0ull;
#pragma unroll
            for (int i = 0; i < 8; i++) {
                ulonglong2 wv = wp[i];
                ulonglong2 hv = hp[i];
                a0 = fma2(wv.x, hv.x, a0);
                a1 = fma2(wv.y, hv.y, a1);
            }
            u64 sx = add2(a0, a1);
            float x = (f2lo(sx) + f2hi(sx)) + blin;              // == out(t-1)
            if (cj == 0) out[(size_t)(b0 + ce) * STEPS + (t - 1)] = x;

            float zi = fmaf(sh_wih1[cj],          x, sh_zA[ce][cj]);
            float zf = fmaf(sh_wih1[Hh + cj],     x, sh_zA[ce][Hh + cj]);
            float zg = fmaf(sh_wih1[2 * Hh + cj], x, sh_zA[ce][2 * Hh + cj]);
            float zo = fmaf(sh_wih1[3 * Hh + cj], x, sh_zA[ce][3 * Hh + cj]);
            float cn = fmaf(sigm(zf), c1, sigm(zi) * tanh_(zg));
            c1 = cn;
            sh_h1[ce][cj] = sigm(zo) * tanh_(cn);
        }
        __syncthreads();                 // B

        // P3: layer-2 gate pre-activations
#pragma unroll
        for (int e = 0; e < EPB; e++) {
            const ulonglong2* h1p = (const ulonglong2*)sh_h1[e];
            const ulonglong2* h2p = (const ulonglong2*)sh_h2[e];
            u64 a0 = 0ull, a1 = 0ull, a2 = 0ull, a3 = 0ull;
#pragma unroll
            for (int i = 0; i < 8; i++) {
                ulonglong2 hv1 = h1p[i];
                ulonglong2 hv2 = h2p[i];
                a0 = fma2(wih2p[2 * i],     hv1.x, a0);
                a1 = fma2(wih2p[2 * i + 1], hv1.y, a1);
                a2 = fma2(whh2p[2 * i],     hv2.x, a2);
                a3 = fma2(whh2p[2 * i + 1], hv2.y, a3);
            }
            u64 s = add2(add2(a0, a1), add2(a2, a3));
            sh_zB[e][r] = bb2 + (f2lo(s) + f2hi(s));
        }
        __syncthreads();                 // C

        // P4: layer-2 combine only
        if (front) {
            float zi = sh_zB[ce][cj],          zf = sh_zB[ce][Hh + cj];
            float zg = sh_zB[ce][2 * Hh + cj], zo = sh_zB[ce][3 * Hh + cj];
            float cn = fmaf(sigm(zf), c2, sigm(zi) * tanh_(zg));
            c2 = cn;
            sh_h2[ce][cj] = sigm(zo) * tanh_(cn);
        }
    }

    // Final output: out[STEPS-1] = W_lin @ h2(final) + b_lin
    __syncthreads();
    if (front && cj == 0) {
        const ulonglong2* wp = (const ulonglong2*)sh_wl;
        const ulonglong2* hp = (const ulonglong2*)sh_h2[ce];
        u64 a0 = 0ull, a1 = 0ull;
#pragma unroll
        for (int i = 0; i < 8; i++) {
            ulonglong2 wv = wp[i];
            ulonglong2 hv = hp[i];
            a0 = fma2(wv.x, hv.x, a0);
            a1 = fma2(wv.y, hv.y, a1);
        }
        u64 sx = add2(a0, a1);
        out[(size_t)(b0 + ce) * STEPS + (STEPS - 1)] = (f2lo(sx) + f2hi(sx)) + blin;
    }
}

// Apply linear head to stored TF h2 history: out[b][t] = W_lin @ H2g[b][t] + b_lin
__global__ __launch_bounds__(256) void head_kernel(
    const float* __restrict__ W_lin, const float* __restrict__ b_lin,
    float* __restrict__ out)
{
    const int b = blockIdx.x;
    float4 wv[8];
    const float4* wp = (const float4*)W_lin;
#pragma unroll
    for (int i = 0; i < 8; i++) wv[i] = wp[i];
    const float bl = b_lin[0];

    for (int t = threadIdx.x; t < TIN; t += 256) {
        const float4* hp = (const float4*)(H2g + ((size_t)b * TIN + t) * Hh);
        float acc = bl;
#pragma unroll
        for (int i = 0; i < 8; i++) {
            float4 h = hp[i];
            acc += wv[i].x * h.x + wv[i].y * h.y + wv[i].z * h.z + wv[i].w * h.w;
        }
        out[(size_t)b * STEPS + t] = acc;
    }
}

extern "C" void kernel_launch(void* const* d_in, const int* in_sizes, int n_in,
                              void* d_out, int out_size) {
    const float* input = (const float*)d_in[0];
    const float* W_ih1 = (const float*)d_in[1];
    const float* W_hh1 = (const float*)d_in[2];
    const float* b_ih1 = (const float*)d_in[3];
    const float* b_hh1 = (const float*)d_in[4];
    const float* W_ih2 = (const float*)d_in[5];
    const float* W_hh2 = (const float*)d_in[6];
    const float* b_ih2 = (const float*)d_in[7];
    const float* b_hh2 = (const float*)d_in[8];
    const float* W_lin = (const float*)d_in[9];
    const float* b_lin = (const float*)d_in[10];
    float* out = (float*)d_out;

    lstm_seq_kernel<<<BATCH / EPB, 128>>>(input, W_ih1, W_hh1, b_ih1, b_hh1,
                                          W_ih2, W_hh2, b_ih2, b_hh2,
                                          W_lin, b_lin, out);
    head_kernel<<<BATCH, 256>>>(W_lin, b_lin, out);
}